// round 2
// baseline (speedup 1.0000x reference)
#include <cuda_runtime.h>
#include <math.h>

#define B_ROWS 8192
#define D_DIM  512
#define EPS_PD 1e-6f
#define MARGIN 0.3f

// ---------------- scratch (static device globals: allowed) ----------------
__device__ float g_an[B_ROWS * D_DIM];     // normalized anchors
__device__ float g_pn[B_ROWS * D_DIM];     // normalized positives
__device__ float g_s [2][B_ROWS];          // row sums of normalized (0=a,1=p)
__device__ float g_s2[2][B_ROWS];          // row sumsqs of normalized
__device__ float g_posd2[B_ROWS];          // d2[i,i]
__device__ float g_cj[B_ROWS];             // sp2[j] - 2*eps*sp[j]
#define NSPLIT 8
__device__ float g_pmin[NSPLIT][B_ROWS];   // partial row mins per N-split

// ---------------- helpers ----------------
__device__ __forceinline__ float blockReduceSum128(float v, float* sm) {
    // 128 threads = 4 warps
    #pragma unroll
    for (int o = 16; o >= 1; o >>= 1) v += __shfl_xor_sync(0xffffffffu, v, o);
    int w = threadIdx.x >> 5;
    if ((threadIdx.x & 31) == 0) sm[w] = v;
    __syncthreads();
    float r = sm[0] + sm[1] + sm[2] + sm[3];
    __syncthreads();
    return r;
}

// ---------------- K1: normalize rows, emit sums ----------------
__global__ void normalize_kernel(const float* __restrict__ x) {
    __shared__ float sm[4];
    int row   = blockIdx.x;
    int which = blockIdx.y;                 // 0 = a, 1 = p
    int t     = threadIdx.x;                // 128 threads, 4 floats each
    const float* src = x + ((size_t)row * 2 + which) * D_DIM;
    float4 v = reinterpret_cast<const float4*>(src)[t];

    float ss = v.x*v.x + v.y*v.y + v.z*v.z + v.w*v.w;
    ss = blockReduceSum128(ss, sm);
    float nrm = fmaxf(sqrtf(ss), 1e-12f);
    float inv = 1.0f / nrm;
    v.x *= inv; v.y *= inv; v.z *= inv; v.w *= inv;

    float* dst = (which ? g_pn : g_an) + (size_t)row * D_DIM;
    reinterpret_cast<float4*>(dst)[t] = v;

    float s1 = v.x + v.y + v.z + v.w;
    float s2 = v.x*v.x + v.y*v.y + v.z*v.z + v.w*v.w;
    s1 = blockReduceSum128(s1, sm);
    s2 = blockReduceSum128(s2, sm);
    if (t == 0) {
        g_s [which][row] = s1;
        g_s2[which][row] = s2;
    }
}

// ---------------- K2: diagonal dot -> pos_d2, and cj ----------------
__global__ void diag_kernel() {
    __shared__ float sm[4];
    int i = blockIdx.x;
    int t = threadIdx.x;                    // 128 threads
    float4 a = reinterpret_cast<const float4*>(g_an + (size_t)i * D_DIM)[t];
    float4 p = reinterpret_cast<const float4*>(g_pn + (size_t)i * D_DIM)[t];
    float d = a.x*p.x + a.y*p.y + a.z*p.z + a.w*p.w;
    d = blockReduceSum128(d, sm);
    if (t == 0) {
        float sa  = g_s [0][i], sp  = g_s [1][i];
        float sa2 = g_s2[0][i], sp2 = g_s2[1][i];
        g_posd2[i] = sa2 + sp2 - 2.0f * d
                   + 2.0f * EPS_PD * (sa - sp)
                   + (float)D_DIM * EPS_PD * EPS_PD;
        g_cj[i] = sp2 - 2.0f * EPS_PD * sp;
    }
}

// ---------------- K3: fused GEMM + row-min ----------------
// dot = an @ pn^T ; val[i][j] = cj[j] - 2*dot[i][j] ; rowmin over j != i.
// Block tile 128x128, thread tile 8x8, BK=16. Grid: (64 M-tiles, NSPLIT).
#define BM 128
#define BN 128
#define BK 16

__global__ __launch_bounds__(256, 2) void gemm_min_kernel() {
    __shared__ float As[BK][BM + 4];
    __shared__ float Bs[BK][BN + 4];

    const int bm = blockIdx.x;             // 0..63
    const int ns = blockIdx.y;             // 0..NSPLIT-1
    const int t  = threadIdx.x;            // 0..255
    const int tx = t & 15;                 // col group
    const int ty = t >> 4;                 // row group
    const int row0 = bm * BM;
    const int NRANGE = B_ROWS / NSPLIT;    // 1024 cols per split

    float rmin[8];
    #pragma unroll
    for (int r = 0; r < 8; r++) rmin[r] = INFINITY;

    for (int nt = 0; nt < NRANGE / BN; nt++) {     // 8 N-tiles
        const int col0 = ns * NRANGE + nt * BN;

        float acc[8][8];
        #pragma unroll
        for (int r = 0; r < 8; r++)
            #pragma unroll
            for (int c = 0; c < 8; c++) acc[r][c] = 0.0f;

        for (int k0 = 0; k0 < D_DIM; k0 += BK) {
            // load 128x16 A and B tiles (512 float4 each, 2 per thread)
            #pragma unroll
            for (int l = 0; l < 2; l++) {
                int idx = t + l * 256;             // 0..511
                int r   = idx >> 2;                // tile row 0..127
                int kq  = (idx & 3) * 4;           // k sub-offset 0,4,8,12
                float4 va = *reinterpret_cast<const float4*>(
                    &g_an[(size_t)(row0 + r) * D_DIM + k0 + kq]);
                As[kq + 0][r] = va.x; As[kq + 1][r] = va.y;
                As[kq + 2][r] = va.z; As[kq + 3][r] = va.w;
                float4 vb = *reinterpret_cast<const float4*>(
                    &g_pn[(size_t)(col0 + r) * D_DIM + k0 + kq]);
                Bs[kq + 0][r] = vb.x; Bs[kq + 1][r] = vb.y;
                Bs[kq + 2][r] = vb.z; Bs[kq + 3][r] = vb.w;
            }
            __syncthreads();

            #pragma unroll
            for (int kk = 0; kk < BK; kk++) {
                float a[8], b[8];
                *reinterpret_cast<float4*>(&a[0]) =
                    *reinterpret_cast<float4*>(&As[kk][ty * 8]);
                *reinterpret_cast<float4*>(&a[4]) =
                    *reinterpret_cast<float4*>(&As[kk][ty * 8 + 4]);
                *reinterpret_cast<float4*>(&b[0]) =
                    *reinterpret_cast<float4*>(&Bs[kk][tx * 8]);
                *reinterpret_cast<float4*>(&b[4]) =
                    *reinterpret_cast<float4*>(&Bs[kk][tx * 8 + 4]);
                #pragma unroll
                for (int r = 0; r < 8; r++)
                    #pragma unroll
                    for (int c = 0; c < 8; c++)
                        acc[r][c] = fmaf(a[r], b[c], acc[r][c]);
            }
            __syncthreads();
        }

        // epilogue: val = cj[j] - 2*dot, masked diagonal, running min
        #pragma unroll
        for (int c = 0; c < 8; c++) {
            int gn = col0 + tx * 8 + c;
            float cjv = g_cj[gn];
            #pragma unroll
            for (int r = 0; r < 8; r++) {
                int gm = row0 + ty * 8 + r;
                float val = cjv - 2.0f * acc[r][c];
                if (gn != gm) rmin[r] = fminf(rmin[r], val);
            }
        }
    }

    // reduce min across the 16 threads (tx) sharing each row group
    #pragma unroll
    for (int r = 0; r < 8; r++) {
        float v = rmin[r];
        #pragma unroll
        for (int off = 8; off >= 1; off >>= 1)
            v = fminf(v, __shfl_xor_sync(0xffffffffu, v, off));
        if (tx == 0) g_pmin[ns][row0 + ty * 8 + r] = v;
    }
}

// ---------------- K4: finalize loss ----------------
__global__ void finalize_kernel(float* __restrict__ out) {
    __shared__ float sm[8];
    int t = threadIdx.x;                    // 256 threads, 1 block
    float sum = 0.0f;
    for (int i = t; i < B_ROWS; i += 256) {
        float m = INFINITY;
        #pragma unroll
        for (int s = 0; s < NSPLIT; s++) m = fminf(m, g_pmin[s][i]);
        float negd2 = g_s2[0][i] + 2.0f * EPS_PD * g_s[0][i]
                    + (float)D_DIM * EPS_PD * EPS_PD + m;
        float v = g_posd2[i] - negd2 + MARGIN;
        sum += fmaxf(v, 0.0f);
    }
    // 8-warp reduction
    #pragma unroll
    for (int o = 16; o >= 1; o >>= 1) sum += __shfl_xor_sync(0xffffffffu, sum, o);
    int w = t >> 5;
    if ((t & 31) == 0) sm[w] = sum;
    __syncthreads();
    if (t == 0) {
        float tot = 0.0f;
        #pragma unroll
        for (int w2 = 0; w2 < 8; w2++) tot += sm[w2];
        out[0] = tot / (float)B_ROWS;
    }
}

// ---------------- launch ----------------
extern "C" void kernel_launch(void* const* d_in, const int* in_sizes, int n_in,
                              void* d_out, int out_size) {
    const float* x = (const float*)d_in[0];
    float* out = (float*)d_out;

    normalize_kernel<<<dim3(B_ROWS, 2), 128>>>(x);
    diag_kernel<<<B_ROWS, 128>>>();
    gemm_min_kernel<<<dim3(B_ROWS / BM, NSPLIT), 256>>>();
    finalize_kernel<<<1, 256>>>(out);
}

// round 6
// speedup vs baseline: 10.1947x; 10.1947x over previous
#include <cuda_runtime.h>
#include <cuda_bf16.h>
#include <math.h>
#include <stdint.h>

#define B_ROWS 8192
#define D_DIM  512
#define EPS_PD 1e-6f
#define MARGIN 0.3f

// GEMM tiling: CTA 128x128, 8 warps (2x4), warp 64x32, BK=64
#define BT     128
#define BK     64
#define NCHUNK (D_DIM / BK)          // 8
#define NT     (B_ROWS / BT)         // 64 tiles each dim

// SMEM layout (dynamic): A/B double-buffered, 128 rows x 128B each
#define A_BYTES   (BT * 128)         // 16384
#define OFF_A0    0
#define OFF_B0    (A_BYTES)
#define OFF_A1    (2 * A_BYTES)
#define OFF_B1    (3 * A_BYTES)
#define OFF_CJ    (4 * A_BYTES)      // 128 floats
#define OFF_RMIN  (OFF_CJ + 512)     // 128 x 4 floats
#define SMEM_TOTAL (OFF_RMIN + 128 * 4 * 4)   // 68096

// ---------------- device scratch ----------------
__device__ __align__(16) __nv_bfloat16 g_anb[B_ROWS * D_DIM];
__device__ __align__(16) __nv_bfloat16 g_pnb[B_ROWS * D_DIM];
__device__ float g_sa[B_ROWS], g_sa2[B_ROWS], g_posd2[B_ROWS], g_cj[B_ROWS];
__device__ float g_pmin[NT][B_ROWS];
__device__ float g_bsum[32];

// ---------------- helpers ----------------
__device__ __forceinline__ uint32_t smem_u32(const void* p) {
    uint32_t a;
    asm("{ .reg .u64 t; cvta.to.shared.u64 t, %1; cvt.u32.u64 %0, t; }"
        : "=r"(a) : "l"(p));
    return a;
}
// swizzle within 8-row group: byte col ^ ((row&7)<<4)
__device__ __forceinline__ uint32_t swz(uint32_t row, uint32_t colByte) {
    return row * 128u + (colByte ^ ((row & 7u) << 4));
}

#define CP_ASYNC16(dst, src) \
    asm volatile("cp.async.cg.shared.global [%0], [%1], 16;" :: "r"(dst), "l"(src) : "memory")
#define CP_COMMIT() asm volatile("cp.async.commit_group;" ::: "memory")

__device__ __forceinline__ void ldsm_x4(uint32_t addr, uint32_t& r0, uint32_t& r1,
                                        uint32_t& r2, uint32_t& r3) {
    asm volatile("ldmatrix.sync.aligned.m8n8.x4.shared.b16 {%0,%1,%2,%3}, [%4];"
                 : "=r"(r0), "=r"(r1), "=r"(r2), "=r"(r3) : "r"(addr));
}
__device__ __forceinline__ void mma16816(float& c0, float& c1, float& c2, float& c3,
                                         uint32_t a0, uint32_t a1, uint32_t a2, uint32_t a3,
                                         uint32_t b0, uint32_t b1) {
    asm volatile("mma.sync.aligned.m16n8k16.row.col.f32.bf16.bf16.f32 "
                 "{%0,%1,%2,%3}, {%4,%5,%6,%7}, {%8,%9}, {%0,%1,%2,%3};"
                 : "+f"(c0), "+f"(c1), "+f"(c2), "+f"(c3)
                 : "r"(a0), "r"(a1), "r"(a2), "r"(a3), "r"(b0), "r"(b1));
}

__device__ __forceinline__ float blockReduceSum(float v, float* sm, int nwarp) {
    #pragma unroll
    for (int o = 16; o >= 1; o >>= 1) v += __shfl_xor_sync(0xffffffffu, v, o);
    int w = threadIdx.x >> 5;
    if ((threadIdx.x & 31) == 0) sm[w] = v;
    __syncthreads();
    float r = 0.0f;
    for (int i = 0; i < nwarp; i++) r += sm[i];
    __syncthreads();
    return r;
}

// ---------------- K1: normalize rows -> bf16 + per-row scalars ----------------
__global__ void normalize_kernel(const float* __restrict__ x) {
    __shared__ float sm[4];
    int row = blockIdx.x;
    int t   = threadIdx.x;                 // 128 threads x 4 floats
    const float4* xa = reinterpret_cast<const float4*>(x + (size_t)row * 2 * D_DIM);
    const float4* xp = reinterpret_cast<const float4*>(x + (size_t)row * 2 * D_DIM + D_DIM);
    float4 a = xa[t];
    float4 p = xp[t];

    float ssa = a.x*a.x + a.y*a.y + a.z*a.z + a.w*a.w;
    float ssp = p.x*p.x + p.y*p.y + p.z*p.z + p.w*p.w;
    ssa = blockReduceSum(ssa, sm, 4);
    ssp = blockReduceSum(ssp, sm, 4);
    float inva = 1.0f / fmaxf(sqrtf(ssa), 1e-12f);
    float invp = 1.0f / fmaxf(sqrtf(ssp), 1e-12f);
    a.x *= inva; a.y *= inva; a.z *= inva; a.w *= inva;
    p.x *= invp; p.y *= invp; p.z *= invp; p.w *= invp;

    __nv_bfloat162* oa = reinterpret_cast<__nv_bfloat162*>(g_anb + (size_t)row * D_DIM);
    __nv_bfloat162* op = reinterpret_cast<__nv_bfloat162*>(g_pnb + (size_t)row * D_DIM);
    oa[2*t]   = __floats2bfloat162_rn(a.x, a.y);
    oa[2*t+1] = __floats2bfloat162_rn(a.z, a.w);
    op[2*t]   = __floats2bfloat162_rn(p.x, p.y);
    op[2*t+1] = __floats2bfloat162_rn(p.z, p.w);

    float s1a = a.x + a.y + a.z + a.w;
    float s1p = p.x + p.y + p.z + p.w;
    float dot = a.x*p.x + a.y*p.y + a.z*p.z + a.w*p.w;
    float s2a = a.x*a.x + a.y*a.y + a.z*a.z + a.w*a.w;
    float s2p = p.x*p.x + p.y*p.y + p.z*p.z + p.w*p.w;
    s1a = blockReduceSum(s1a, sm, 4);
    s1p = blockReduceSum(s1p, sm, 4);
    dot = blockReduceSum(dot, sm, 4);
    s2a = blockReduceSum(s2a, sm, 4);
    s2p = blockReduceSum(s2p, sm, 4);
    if (t == 0) {
        g_sa[row]  = s1a;
        g_sa2[row] = s2a;
        g_cj[row]  = s2p - 2.0f * EPS_PD * s1p;
        g_posd2[row] = s2a + s2p - 2.0f * dot
                     + 2.0f * EPS_PD * (s1a - s1p)
                     + (float)D_DIM * EPS_PD * EPS_PD;
    }
}

// ---------------- K2: bf16 mma.sync GEMM + fused row-min ----------------
// blockIdx.x = N tile (fast-varying -> consecutive CTAs share A rows in L2)
// blockIdx.y = M tile
__global__ __launch_bounds__(256, 2) void gemm_min_kernel() {
    extern __shared__ char smem[];
    const uint32_t sb = smem_u32(smem);
    const int t    = threadIdx.x;          // 256 threads, 8 warps
    const int wid  = t >> 5;
    const int lane = t & 31;
    const int wm   = wid >> 2;             // 0..1 : M half
    const int wn   = wid & 3;              // 0..3 : N quarter
    const int row0 = blockIdx.y * BT;
    const int col0 = blockIdx.x * BT;

    if (t < 128) reinterpret_cast<float*>(smem + OFF_CJ)[t] = g_cj[col0 + t];

    const char* Agc = reinterpret_cast<const char*>(g_anb);
    const char* Bgc = reinterpret_cast<const char*>(g_pnb);

    // lane-fixed ldmatrix base offsets (ks=0); +32B per k16 step
    uint32_t aOff[4];
    {
        int tIdx = lane >> 3, r = lane & 7;
        #pragma unroll
        for (int mi = 0; mi < 4; mi++) {
            uint32_t m  = (uint32_t)(wm * 64 + mi * 16 + (tIdx & 1) * 8 + r);
            uint32_t cb = (uint32_t)((tIdx >> 1) * 16);
            aOff[mi] = swz(m, cb);
        }
    }
    uint32_t bOff[2];
    {
        int tIdx = lane >> 3, r = lane & 7;
        #pragma unroll
        for (int nt2 = 0; nt2 < 2; nt2++) {
            uint32_t n  = (uint32_t)(wn * 32 + nt2 * 16 + (tIdx >> 1) * 8 + r);
            uint32_t cb = (uint32_t)((tIdx & 1) * 16);
            bOff[nt2] = swz(n, cb);
        }
    }

    float acc[4][4][4];
    #pragma unroll
    for (int mi = 0; mi < 4; mi++)
        #pragma unroll
        for (int ni = 0; ni < 4; ni++)
            #pragma unroll
            for (int k = 0; k < 4; k++) acc[mi][ni][k] = 0.0f;

    // prefetch chunk 0
    {
        #pragma unroll
        for (int j = 0; j < 4; j++) {
            int i = t + j * 256;
            int r = i >> 3, s = i & 7;
            CP_ASYNC16(sb + OFF_A0 + swz((uint32_t)r, (uint32_t)(s * 16)),
                       Agc + ((size_t)(row0 + r) * D_DIM + s * 8) * 2);
        }
        #pragma unroll
        for (int j = 0; j < 4; j++) {
            int i = t + j * 256;
            int r = i >> 3, s = i & 7;
            CP_ASYNC16(sb + OFF_B0 + swz((uint32_t)r, (uint32_t)(s * 16)),
                       Bgc + ((size_t)(col0 + r) * D_DIM + s * 8) * 2);
        }
        CP_COMMIT();
    }

    for (int c = 0; c < NCHUNK; c++) {
        if (c + 1 < NCHUNK) {
            uint32_t abase = sb + (((c + 1) & 1) ? OFF_A1 : OFF_A0);
            uint32_t bbase = sb + (((c + 1) & 1) ? OFF_B1 : OFF_B0);
            int kq = (c + 1) * BK;
            #pragma unroll
            for (int j = 0; j < 4; j++) {
                int i = t + j * 256;
                int r = i >> 3, s = i & 7;
                CP_ASYNC16(abase + swz((uint32_t)r, (uint32_t)(s * 16)),
                           Agc + ((size_t)(row0 + r) * D_DIM + kq + s * 8) * 2);
            }
            #pragma unroll
            for (int j = 0; j < 4; j++) {
                int i = t + j * 256;
                int r = i >> 3, s = i & 7;
                CP_ASYNC16(bbase + swz((uint32_t)r, (uint32_t)(s * 16)),
                           Bgc + ((size_t)(col0 + r) * D_DIM + kq + s * 8) * 2);
            }
            CP_COMMIT();
            asm volatile("cp.async.wait_group 1;" ::: "memory");
        } else {
            asm volatile("cp.async.wait_group 0;" ::: "memory");
        }
        __syncthreads();

        const uint32_t aB = sb + ((c & 1) ? OFF_A1 : OFF_A0);
        const uint32_t bB = sb + ((c & 1) ? OFF_B1 : OFF_B0);

        #pragma unroll
        for (int ks = 0; ks < 4; ks++) {
            uint32_t af[4][4];
            uint32_t bf[4][2];
            #pragma unroll
            for (int mi = 0; mi < 4; mi++)
                ldsm_x4(aB + aOff[mi] + ks * 32,
                        af[mi][0], af[mi][1], af[mi][2], af[mi][3]);
            #pragma unroll
            for (int nt2 = 0; nt2 < 2; nt2++) {
                uint32_t r0, r1, r2, r3;
                ldsm_x4(bB + bOff[nt2] + ks * 32, r0, r1, r2, r3);
                bf[nt2 * 2][0] = r0;  bf[nt2 * 2][1] = r1;
                bf[nt2 * 2 + 1][0] = r2; bf[nt2 * 2 + 1][1] = r3;
            }
            #pragma unroll
            for (int mi = 0; mi < 4; mi++)
                #pragma unroll
                for (int ni = 0; ni < 4; ni++)
                    mma16816(acc[mi][ni][0], acc[mi][ni][1], acc[mi][ni][2], acc[mi][ni][3],
                             af[mi][0], af[mi][1], af[mi][2], af[mi][3],
                             bf[ni][0], bf[ni][1]);
        }
        __syncthreads();
    }

    // epilogue: val = cj[j] - 2*dot, diagonal masked, fused row-min
    const float* cjs = reinterpret_cast<const float*>(smem + OFF_CJ);
    float* rminS = reinterpret_cast<float*>(smem + OFF_RMIN);   // [128][4]
    const int g  = lane >> 2;
    const int t2 = (lane & 3) * 2;

    #pragma unroll
    for (int mi = 0; mi < 4; mi++) {
        float rlow = INFINITY, rhigh = INFINITY;
        const int rowLow  = row0 + wm * 64 + mi * 16 + g;
        const int rowHigh = rowLow + 8;
        #pragma unroll
        for (int ni = 0; ni < 4; ni++) {
            #pragma unroll
            for (int d = 0; d < 2; d++) {
                int cl = wn * 32 + ni * 8 + t2 + d;
                int cg = col0 + cl;
                float cjv = cjs[cl];
                float vl = cjv - 2.0f * acc[mi][ni][d];
                float vh = cjv - 2.0f * acc[mi][ni][2 + d];
                if (cg != rowLow)  rlow  = fminf(rlow, vl);
                if (cg != rowHigh) rhigh = fminf(rhigh, vh);
            }
        }
        #pragma unroll
        for (int o = 1; o <= 2; o <<= 1) {
            rlow  = fminf(rlow,  __shfl_xor_sync(0xffffffffu, rlow, o));
            rhigh = fminf(rhigh, __shfl_xor_sync(0xffffffffu, rhigh, o));
        }
        if ((lane & 3) == 0) {
            rminS[(wm * 64 + mi * 16 + g) * 4 + wn]     = rlow;
            rminS[(wm * 64 + mi * 16 + 8 + g) * 4 + wn] = rhigh;
        }
    }
    __syncthreads();
    if (t < 128) {
        float m = fminf(fminf(rminS[t * 4 + 0], rminS[t * 4 + 1]),
                        fminf(rminS[t * 4 + 2], rminS[t * 4 + 3]));
        g_pmin[blockIdx.x][row0 + t] = m;
    }
}

// ---------------- K3/K4: finalize ----------------
__global__ void finalize1_kernel() {
    __shared__ float sm[8];
    int i = blockIdx.x * 256 + threadIdx.x;       // 32 x 256 = 8192
    float m = INFINITY;
    for (int s = 0; s < NT; s++) m = fminf(m, g_pmin[s][i]);
    float negd2 = g_sa2[i] + 2.0f * EPS_PD * g_sa[i]
                + (float)D_DIM * EPS_PD * EPS_PD + m;
    float v = fmaxf(g_posd2[i] - negd2 + MARGIN, 0.0f);
    v = blockReduceSum(v, sm, 8);
    if (threadIdx.x == 0) g_bsum[blockIdx.x] = v;
}

__global__ void finalize2_kernel(float* __restrict__ out) {
    float v = g_bsum[threadIdx.x];                 // 32 threads
    #pragma unroll
    for (int o = 16; o >= 1; o >>= 1) v += __shfl_xor_sync(0xffffffffu, v, o);
    if (threadIdx.x == 0) out[0] = v / (float)B_ROWS;
}

// ---------------- launch ----------------
extern "C" void kernel_launch(void* const* d_in, const int* in_sizes, int n_in,
                              void* d_out, int out_size) {
    const float* x = (const float*)d_in[0];
    float* out = (float*)d_out;

    cudaFuncSetAttribute(gemm_min_kernel,
                         cudaFuncAttributeMaxDynamicSharedMemorySize, SMEM_TOTAL);

    normalize_kernel<<<B_ROWS, 128>>>(x);
    gemm_min_kernel<<<dim3(NT, NT), 256, SMEM_TOTAL>>>();
    finalize1_kernel<<<32, 256>>>();
    finalize2_kernel<<<1, 32>>>(out);
}